// round 3
// baseline (speedup 1.0000x reference)
#include <cuda_runtime.h>
#include <math.h>

// ---------------- problem constants ----------------
#define TOKENS 4096      // B(4) * 32 * 32
#define EMB    768
#define NHEAD  12
#define HD     64
#define SEQ    1024      // tokens per image
#define BHEADS 48        // B * NHEAD
#define MLPD   3072
#define GRID32 32

// ---------------- scratch (device globals; no allocs allowed) ----------------
__device__ float g_h[TOKENS * EMB];
__device__ float g_xn[TOKENS * EMB];
__device__ float g_col[TOKENS * EMB];
__device__ float g_q[BHEADS * SEQ * HD];
__device__ float g_k[BHEADS * SEQ * HD];
__device__ float g_v[BHEADS * SEQ * HD];
__device__ float g_relh[BHEADS * SEQ * GRID32];
__device__ float g_relw[BHEADS * SEQ * GRID32];
__device__ float g_S[(size_t)BHEADS * SEQ * SEQ];   // 201 MB
__device__ float g_attn[TOKENS * EMB];
__device__ float g_mlp[TOKENS * MLPD];

enum { EPI_CONVPOS = 1, EPI_QKV = 2, EPI_SREL = 3, EPI_AV = 4, EPI_BIASRES = 5, EPI_GELU = 6 };

// ---------------- generic tiled SGEMM with fused epilogues ----------------
// C[M,N] (+epi) = A[M,K] * B; B is K x N row-major (BT=false) or N x K row-major (BT=true).
// Requirements (all satisfied by this problem): M % BM == 0, N % BN == 0, K % BK == 0, K % 4 == 0.
template <int BM, int BN, int BK, int TM, int TN, int EPI, bool BT>
__global__ __launch_bounds__((BM / TM) * (BN / TN))
void gemm_kernel(const float* __restrict__ A, const float* __restrict__ B,
                 float* __restrict__ C, int M, int N, int K,
                 size_t sA, size_t sB, size_t sC,
                 const float* __restrict__ bias,
                 const float* __restrict__ aux1,
                 const float* __restrict__ aux2,
                 float* __restrict__ p0, float* __restrict__ p1, float* __restrict__ p2,
                 float scale)
{
    constexpr int THREADS = (BM / TM) * (BN / TN);
    const int z = blockIdx.z;
    A += (size_t)z * sA;
    B += (size_t)z * sB;
    if (C) C += (size_t)z * sC;

    __shared__ float As[BK][BM];
    __shared__ float Bs[BK][BN];

    const int tid = threadIdx.x;
    const int tx = tid % (BN / TN);
    const int ty = tid / (BN / TN);
    const int row0 = blockIdx.y * BM;
    const int col0 = blockIdx.x * BN;

    float acc[TM][TN];
#pragma unroll
    for (int i = 0; i < TM; i++)
#pragma unroll
        for (int j = 0; j < TN; j++) acc[i][j] = 0.f;

    // A tile load mapping: BM rows * BK cols, float4 along K. Needs BM*BK/4 == THREADS.
    static_assert(BM * BK / 4 == THREADS, "A load mapping");
    const int aRow = tid / (BK / 4);
    const int aCol = (tid % (BK / 4)) * 4;

    for (int k0 = 0; k0 < K; k0 += BK) {
        float4 av = *reinterpret_cast<const float4*>(A + (size_t)(row0 + aRow) * K + k0 + aCol);
        As[aCol + 0][aRow] = av.x;
        As[aCol + 1][aRow] = av.y;
        As[aCol + 2][aRow] = av.z;
        As[aCol + 3][aRow] = av.w;

        constexpr int BLOADS = BN * BK / 4;
        if (BLOADS == THREADS || tid < BLOADS) {
            if (BT) {
                const int n = tid / (BK / 4);
                const int c = (tid % (BK / 4)) * 4;
                float4 bv = *reinterpret_cast<const float4*>(B + (size_t)(col0 + n) * K + k0 + c);
                Bs[c + 0][n] = bv.x;
                Bs[c + 1][n] = bv.y;
                Bs[c + 2][n] = bv.z;
                Bs[c + 3][n] = bv.w;
            } else {
                const int r = tid / (BN / 4);
                const int c = (tid % (BN / 4)) * 4;
                *reinterpret_cast<float4*>(&Bs[r][c]) =
                    *reinterpret_cast<const float4*>(B + (size_t)(k0 + r) * N + col0 + c);
            }
        }
        __syncthreads();

#pragma unroll
        for (int kk = 0; kk < BK; kk++) {
            float a[TM], b[TN];
#pragma unroll
            for (int i = 0; i < TM; i++) a[i] = As[kk][ty * TM + i];
#pragma unroll
            for (int j = 0; j < TN; j++) b[j] = Bs[kk][tx * TN + j];
#pragma unroll
            for (int i = 0; i < TM; i++)
#pragma unroll
                for (int j = 0; j < TN; j++) acc[i][j] = fmaf(a[i], b[j], acc[i][j]);
        }
        __syncthreads();
    }

#pragma unroll
    for (int i = 0; i < TM; i++) {
        const int m = row0 + ty * TM + i;
#pragma unroll
        for (int j = 0; j < TN; j++) {
            const int n = col0 + tx * TN + j;
            float v = acc[i][j];
            if constexpr (EPI == EPI_CONVPOS) {
                // conv bias + positional embedding
                v += bias[n] + aux1[(size_t)(m & (SEQ - 1)) * EMB + n];
                C[(size_t)m * N + n] = v;
            } else if constexpr (EPI == EPI_QKV) {
                v += bias[n];
                const int which = n / EMB;
                const int r = n - which * EMB;
                const int head = r >> 6;
                const int d = r & 63;
                const int b = m >> 10;
                const int nl = m & (SEQ - 1);
                float* dst = (which == 0) ? p0 : ((which == 1) ? p1 : p2);
                dst[((size_t)(b * NHEAD + head) * SEQ + nl) * HD + d] = v;
            } else if constexpr (EPI == EPI_SREL) {
                // S = scale*(q.kT) + rel_h[q, kh] + rel_w[q, kw]
                v = v * scale + aux1[((size_t)z * SEQ + m) * GRID32 + (n >> 5)]
                              + aux2[((size_t)z * SEQ + m) * GRID32 + (n & 31)];
                C[(size_t)m * N + n] = v;
            } else if constexpr (EPI == EPI_AV) {
                const int b = z / NHEAD;
                const int head = z - b * NHEAD;
                p0[(size_t)(b * SEQ + m) * EMB + head * HD + n] = v;
            } else if constexpr (EPI == EPI_BIASRES) {
                v += bias[n] + aux1[(size_t)m * N + n];
                C[(size_t)m * N + n] = v;
            } else if constexpr (EPI == EPI_GELU) {
                v += bias[n];
                v = 0.5f * v * (1.f + erff(v * 0.70710678118654752f));
                C[(size_t)m * N + n] = v;
            }
        }
    }
}

// ---------------- im2col for the 16x16/stride-16 patch conv ----------------
__global__ void im2col_kernel(const float* __restrict__ x, float* __restrict__ col)
{
    int idx = blockIdx.x * blockDim.x + threadIdx.x;
    if (idx >= TOKENS * EMB) return;
    int m = idx / EMB, kk = idx - m * EMB;
    int b = m >> 10, p = m & 1023, ph = p >> 5, pw = p & 31;
    int c = kk >> 8, r = kk & 255, kh = r >> 4, kw = r & 15;
    col[idx] = x[((size_t)(b * 3 + c) * 512 + (ph * 16 + kh)) * 512 + pw * 16 + kw];
}

// ---------------- layernorm: one block per token row ----------------
__device__ __forceinline__ float warpReduceSum(float v)
{
#pragma unroll
    for (int o = 16; o; o >>= 1) v += __shfl_xor_sync(0xffffffffu, v, o);
    return v;
}

__global__ __launch_bounds__(256)
void ln_kernel(const float* __restrict__ in, const float* __restrict__ w,
               const float* __restrict__ b, float* __restrict__ out)
{
    __shared__ float sh[8];
    const int row = blockIdx.x;
    const int t = threadIdx.x;
    const float* x = in + (size_t)row * EMB;
    float v0 = x[t], v1 = x[t + 256], v2 = x[t + 512];
    float s = warpReduceSum(v0 + v1 + v2);
    if ((t & 31) == 0) sh[t >> 5] = s;
    __syncthreads();
    float mean = (sh[0] + sh[1] + sh[2] + sh[3] + sh[4] + sh[5] + sh[6] + sh[7]) * (1.f / EMB);
    float d0 = v0 - mean, d1 = v1 - mean, d2 = v2 - mean;
    __syncthreads();
    float s2 = warpReduceSum(d0 * d0 + d1 * d1 + d2 * d2);
    if ((t & 31) == 0) sh[t >> 5] = s2;
    __syncthreads();
    float var = (sh[0] + sh[1] + sh[2] + sh[3] + sh[4] + sh[5] + sh[6] + sh[7]) * (1.f / EMB);
    float rstd = rsqrtf(var + 1e-5f);
    float* o = out + (size_t)row * EMB;
    o[t]       = d0 * rstd * w[t]       + b[t];
    o[t + 256] = d1 * rstd * w[t + 256] + b[t + 256];
    o[t + 512] = d2 * rstd * w[t + 512] + b[t + 512];
}

// ---------------- decomposed rel-pos: rel_h/rel_w dot products ----------------
// block = one (bh, q-token); threads 0..31 -> rel_h over kh, 32..63 -> rel_w over kw
__global__ __launch_bounds__(64)
void rel_kernel(const float* __restrict__ q,
                const float* __restrict__ rph, const float* __restrict__ rpw,
                float* __restrict__ relh, float* __restrict__ relw)
{
    const int bq = blockIdx.x;            // bh*SEQ + n
    const int p = bq & (SEQ - 1);
    const int qh = p >> 5, qw = p & 31;
    __shared__ float qs[HD];
    const int t = threadIdx.x;
    qs[t] = q[(size_t)bq * HD + t];
    __syncthreads();
    const int kidx = t & 31;
    const float* tab = (t < 32) ? (rph + (qh - kidx + 31) * HD)
                                : (rpw + (qw - kidx + 31) * HD);
    float s = 0.f;
#pragma unroll
    for (int d = 0; d < HD; d++) s = fmaf(qs[d], tab[d], s);
    if (t < 32) relh[(size_t)bq * GRID32 + kidx] = s;
    else        relw[(size_t)bq * GRID32 + kidx] = s;
}

// ---------------- row softmax over SEQ=1024 ----------------
__global__ __launch_bounds__(256)
void softmax_kernel(float* __restrict__ S)
{
    __shared__ float sh[8];
    const size_t row = blockIdx.x;
    float* p = S + row * SEQ;
    const int t = threadIdx.x;
    float v0 = p[t], v1 = p[t + 256], v2 = p[t + 512], v3 = p[t + 768];
    float mx = fmaxf(fmaxf(v0, v1), fmaxf(v2, v3));
#pragma unroll
    for (int o = 16; o; o >>= 1) mx = fmaxf(mx, __shfl_xor_sync(0xffffffffu, mx, o));
    if ((t & 31) == 0) sh[t >> 5] = mx;
    __syncthreads();
    mx = fmaxf(fmaxf(fmaxf(sh[0], sh[1]), fmaxf(sh[2], sh[3])),
               fmaxf(fmaxf(sh[4], sh[5]), fmaxf(sh[6], sh[7])));
    v0 = __expf(v0 - mx); v1 = __expf(v1 - mx);
    v2 = __expf(v2 - mx); v3 = __expf(v3 - mx);
    float s = warpReduceSum(v0 + v1 + v2 + v3);
    __syncthreads();
    if ((t & 31) == 0) sh[t >> 5] = s;
    __syncthreads();
    float inv = 1.f / (sh[0] + sh[1] + sh[2] + sh[3] + sh[4] + sh[5] + sh[6] + sh[7]);
    p[t] = v0 * inv; p[t + 256] = v1 * inv; p[t + 512] = v2 * inv; p[t + 768] = v3 * inv;
}

// ---------------- host orchestration ----------------
extern "C" void kernel_launch(void* const* d_in, const int* in_sizes, int n_in,
                              void* d_out, int out_size)
{
    const float* x      = (const float*)d_in[0];
    const float* conv_w = (const float*)d_in[1];   // (768, 3,16,16) -> N x K (BT)
    const float* conv_b = (const float*)d_in[2];
    const float* pos    = (const float*)d_in[3];
    const float* ln1_w  = (const float*)d_in[4];
    const float* ln1_b  = (const float*)d_in[5];
    const float* qkv_w  = (const float*)d_in[6];   // (4, 768, 2304) K x N
    const float* qkv_b  = (const float*)d_in[7];
    const float* proj_w = (const float*)d_in[8];
    const float* proj_b = (const float*)d_in[9];
    const float* rph    = (const float*)d_in[10];  // (4, 63, 64)
    const float* rpw    = (const float*)d_in[11];
    const float* ln2_w  = (const float*)d_in[12];
    const float* ln2_b  = (const float*)d_in[13];
    const float* fc1_w  = (const float*)d_in[14];
    const float* fc1_b  = (const float*)d_in[15];
    const float* fc2_w  = (const float*)d_in[16];
    const float* fc2_b  = (const float*)d_in[17];

    float *h, *xn, *col, *q, *k, *v, *relh, *relw, *S, *attn, *mlp;
    cudaGetSymbolAddress((void**)&h, g_h);
    cudaGetSymbolAddress((void**)&xn, g_xn);
    cudaGetSymbolAddress((void**)&col, g_col);
    cudaGetSymbolAddress((void**)&q, g_q);
    cudaGetSymbolAddress((void**)&k, g_k);
    cudaGetSymbolAddress((void**)&v, g_v);
    cudaGetSymbolAddress((void**)&relh, g_relh);
    cudaGetSymbolAddress((void**)&relw, g_relw);
    cudaGetSymbolAddress((void**)&S, g_S);
    cudaGetSymbolAddress((void**)&attn, g_attn);
    cudaGetSymbolAddress((void**)&mlp, g_mlp);

    const float scale = 0.125f;  // HD^-0.5

    // patch embed: im2col + GEMM (B transposed) + conv_b + pos_embed
    im2col_kernel<<<(TOKENS * EMB + 255) / 256, 256>>>(x, col);
    gemm_kernel<128, 128, 8, 8, 8, EPI_CONVPOS, true><<<dim3(EMB / 128, TOKENS / 128, 1), 256>>>(
        col, conv_w, h, TOKENS, EMB, EMB, 0, 0, 0,
        conv_b, pos, nullptr, nullptr, nullptr, nullptr, 0.f);

    for (int i = 0; i < 4; i++) {
        // LN1
        ln_kernel<<<TOKENS, 256>>>(h, ln1_w + i * EMB, ln1_b + i * EMB, xn);

        // QKV projection, scattered into per-(b,head) q/k/v layouts
        gemm_kernel<128, 128, 8, 8, 8, EPI_QKV, false><<<dim3(3 * EMB / 128, TOKENS / 128, 1), 256>>>(
            xn, qkv_w + (size_t)i * EMB * 3 * EMB, nullptr, TOKENS, 3 * EMB, EMB, 0, 0, 0,
            qkv_b + (size_t)i * 3 * EMB, nullptr, nullptr, q, k, v, 0.f);

        // decomposed rel-pos dot products
        rel_kernel<<<BHEADS * SEQ, 64>>>(q, rph + (size_t)i * 63 * HD, rpw + (size_t)i * 63 * HD,
                                         relh, relw);

        // S = scale * q @ k^T + rel_h + rel_w   (batched over 48 bh)
        gemm_kernel<128, 128, 8, 8, 8, EPI_SREL, true><<<dim3(SEQ / 128, SEQ / 128, BHEADS), 256>>>(
            q, k, S, SEQ, SEQ, HD,
            (size_t)SEQ * HD, (size_t)SEQ * HD, (size_t)SEQ * SEQ,
            nullptr, relh, relw, nullptr, nullptr, nullptr, scale);

        // softmax rows
        softmax_kernel<<<BHEADS * SEQ, 256>>>(S);

        // O = P @ v, scattered back to token-major (b*SEQ+n, head*64+d)
        gemm_kernel<128, 64, 8, 8, 4, EPI_AV, false><<<dim3(1, SEQ / 128, BHEADS), 256>>>(
            S, v, nullptr, SEQ, HD, SEQ,
            (size_t)SEQ * SEQ, (size_t)SEQ * HD, 0,
            nullptr, nullptr, nullptr, attn, nullptr, nullptr, 0.f);

        // proj + bias + residual
        gemm_kernel<128, 128, 8, 8, 8, EPI_BIASRES, false><<<dim3(EMB / 128, TOKENS / 128, 1), 256>>>(
            attn, proj_w + (size_t)i * EMB * EMB, h, TOKENS, EMB, EMB, 0, 0, 0,
            proj_b + (size_t)i * EMB, h, nullptr, nullptr, nullptr, nullptr, 0.f);

        // LN2
        ln_kernel<<<TOKENS, 256>>>(h, ln2_w + i * EMB, ln2_b + i * EMB, xn);

        // fc1 + exact GELU
        gemm_kernel<128, 128, 8, 8, 8, EPI_GELU, false><<<dim3(MLPD / 128, TOKENS / 128, 1), 256>>>(
            xn, fc1_w + (size_t)i * EMB * MLPD, mlp, TOKENS, MLPD, EMB, 0, 0, 0,
            fc1_b + (size_t)i * MLPD, nullptr, nullptr, nullptr, nullptr, nullptr, 0.f);

        // fc2 + bias + residual (last layer writes straight to d_out)
        float* dst = (i == 3) ? (float*)d_out : h;
        gemm_kernel<128, 128, 8, 8, 8, EPI_BIASRES, false><<<dim3(EMB / 128, TOKENS / 128, 1), 256>>>(
            mlp, fc2_w + (size_t)i * MLPD * EMB, dst, TOKENS, EMB, MLPD, 0, 0, 0,
            fc2_b + (size_t)i * EMB, h, nullptr, nullptr, nullptr, nullptr, 0.f);
    }
}

// round 8
// speedup vs baseline: 1.5498x; 1.5498x over previous
#include <cuda_runtime.h>
#include <math.h>
#include <stdint.h>
#include <mma.h>

using namespace nvcuda;

// ---------------- problem constants ----------------
#define TOKENS 4096      // B(4) * 32 * 32
#define EMB    768
#define NHEAD  12
#define HD     64
#define SEQ    1024      // tokens per image
#define BHEADS 48        // B * NHEAD
#define MLPD   3072
#define GRID32 32

// ---------------- scratch (device globals; no allocs allowed) ----------------
__device__ float g_h[TOKENS * EMB];
__device__ float g_xn[TOKENS * EMB];
__device__ float g_col[TOKENS * EMB];
__device__ float g_q[BHEADS * SEQ * HD];
__device__ float g_k[BHEADS * SEQ * HD];
__device__ float g_v[BHEADS * SEQ * HD];
__device__ float g_relh[BHEADS * SEQ * GRID32];
__device__ float g_relw[BHEADS * SEQ * GRID32];
__device__ float g_S[(size_t)BHEADS * SEQ * SEQ];   // 201 MB
__device__ float g_attn[TOKENS * EMB];
__device__ float g_mlp[TOKENS * MLPD];

// transposed (+tf32-rounded) weights, [N,K] K-major
__device__ float g_cwT[EMB * EMB];
__device__ float g_qkvT[4 * 3 * EMB * EMB];
__device__ float g_projT[4 * EMB * EMB];
__device__ float g_fc1T[4 * MLPD * EMB];
__device__ float g_fc2T[4 * EMB * MLPD];

enum { EPI_CONVPOS = 1, EPI_QKV = 2, EPI_SREL = 3, EPI_AV = 4, EPI_BIASRES = 5, EPI_GELU = 6 };

// ---------------- helpers ----------------
__device__ __forceinline__ float to_tf32(float x)
{
    float r;
    asm("cvt.rna.tf32.f32 %0, %1;" : "=f"(r) : "f"(x));
    return r;
}

__device__ __forceinline__ uint32_t smem_u32(const void* p)
{
    return (uint32_t)__cvta_generic_to_shared(p);
}

__device__ __forceinline__ void cp16(uint32_t dst, const void* src)
{
    asm volatile("cp.async.cg.shared.global [%0], [%1], 16;\n" :: "r"(dst), "l"(src));
}
__device__ __forceinline__ void cp_commit()
{
    asm volatile("cp.async.commit_group;\n" ::: "memory");
}
template <int N>
__device__ __forceinline__ void cp_wait()
{
    asm volatile("cp.async.wait_group %0;\n" :: "n"(N) : "memory");
}

// stage nrows x cfl floats from global (row stride ld) into smem (row stride ss)
template <int NROWS, int CFL, int THREADS>
__device__ __forceinline__ void ld_tile(const float* __restrict__ g, int ld,
                                        float* __restrict__ s, int ss, int tid)
{
    constexpr int CH = NROWS * (CFL / 4);
#pragma unroll
    for (int i = 0; i < (CH + THREADS - 1) / THREADS; i++) {
        int lin = i * THREADS + tid;
        if (CH % THREADS == 0 || lin < CH) {
            int r = lin / (CFL / 4);
            int c = (lin - r * (CFL / 4)) * 4;
            cp16(smem_u32(s + r * ss + c), g + (size_t)r * ld + c);
        }
    }
}

// ---------------- wmma tf32 GEMM with fused epilogues ----------------
// C[M,N] = A[M,K] (row-major) * B ; B is [N,K] (BROW=false, wmma col_major)
// or [K,N] row-major (BROW=true). Batched over blockIdx.z via strides.
template <int BM, int BN, int BK, int WM, int WN, int EPI, bool BROW>
__global__ __launch_bounds__((BM / WM) * (BN / WN) * 32)
void wgemm(const float* __restrict__ A, const float* __restrict__ B,
           float* __restrict__ C, int N, int K,
           size_t sAs, size_t sBs, size_t sCs,
           const float* __restrict__ bias,
           const float* __restrict__ aux1, const float* __restrict__ aux2,
           float* __restrict__ p0, float* __restrict__ p1, float* __restrict__ p2,
           float scale)
{
    constexpr int WARPS_M = BM / WM;
    constexpr int WARPS_N = BN / WN;
    constexpr int THREADS = WARPS_M * WARPS_N * 32;
    constexpr int FM = WM / 16, FN = WN / 16;
    constexpr int SA = BK + 8;                 // A smem stride (floats)
    constexpr int SB = BROW ? (BN + 8) : (BK + 8);
    constexpr int ASZ = BM * SA;
    constexpr int BSZ = BROW ? (BK * SB) : (BN * SB);
    constexpr int STAGE = ASZ + BSZ;
    constexpr int SC = BN + 8;                 // C staging stride
    static_assert(BM * SC <= 2 * STAGE, "C staging fits");

    extern __shared__ float sm[];

    const int z = blockIdx.z;
    A += (size_t)z * sAs;
    B += (size_t)z * sBs;
    if (C) C += (size_t)z * sCs;

    const int tid = threadIdx.x;
    const int wid = tid >> 5;
    const int warpM = wid % WARPS_M;
    const int warpN = wid / WARPS_M;
    const int row0 = blockIdx.y * BM;
    const int col0 = blockIdx.x * BN;

    wmma::fragment<wmma::accumulator, 16, 16, 8, float> acc[FM][FN];
#pragma unroll
    for (int i = 0; i < FM; i++)
#pragma unroll
        for (int j = 0; j < FN; j++) wmma::fill_fragment(acc[i][j], 0.f);

    const int KB = K / BK;

    // prologue: stage 0
    ld_tile<BM, BK, THREADS>(A + (size_t)row0 * K, K, sm, SA, tid);
    if (BROW)
        ld_tile<BK, BN, THREADS>(B + col0, N, sm + ASZ, SB, tid);
    else
        ld_tile<BN, BK, THREADS>(B + (size_t)col0 * K, K, sm + ASZ, SB, tid);
    cp_commit();

    for (int kb = 0; kb < KB; kb++) {
        // prefetch stage kb+1 into other buffer
        if (kb + 1 < KB) {
            float* d = sm + ((kb + 1) & 1) * STAGE;
            ld_tile<BM, BK, THREADS>(A + (size_t)row0 * K + (kb + 1) * BK, K, d, SA, tid);
            if (BROW)
                ld_tile<BK, BN, THREADS>(B + (size_t)(kb + 1) * BK * N + col0, N, d + ASZ, SB, tid);
            else
                ld_tile<BN, BK, THREADS>(B + (size_t)col0 * K + (kb + 1) * BK, K, d + ASZ, SB, tid);
        }
        cp_commit();
        cp_wait<1>();
        __syncthreads();

        const float* As = sm + (kb & 1) * STAGE;
        const float* Bs = As + ASZ;

#pragma unroll
        for (int kk = 0; kk < BK / 8; kk++) {
            wmma::fragment<wmma::matrix_a, 16, 16, 8, wmma::precision::tf32, wmma::row_major> af[FM];
#pragma unroll
            for (int i = 0; i < FM; i++)
                wmma::load_matrix_sync(af[i], As + (warpM * WM + i * 16) * SA + kk * 8, SA);
            if constexpr (BROW) {
                wmma::fragment<wmma::matrix_b, 16, 16, 8, wmma::precision::tf32, wmma::row_major> bf[FN];
#pragma unroll
                for (int j = 0; j < FN; j++)
                    wmma::load_matrix_sync(bf[j], Bs + kk * 8 * SB + warpN * WN + j * 16, SB);
#pragma unroll
                for (int i = 0; i < FM; i++)
#pragma unroll
                    for (int j = 0; j < FN; j++)
                        wmma::mma_sync(acc[i][j], af[i], bf[j], acc[i][j]);
            } else {
                wmma::fragment<wmma::matrix_b, 16, 16, 8, wmma::precision::tf32, wmma::col_major> bf[FN];
#pragma unroll
                for (int j = 0; j < FN; j++)
                    wmma::load_matrix_sync(bf[j], Bs + (warpN * WN + j * 16) * SB + kk * 8, SB);
#pragma unroll
                for (int i = 0; i < FM; i++)
#pragma unroll
                    for (int j = 0; j < FN; j++)
                        wmma::mma_sync(acc[i][j], af[i], bf[j], acc[i][j]);
            }
        }
        __syncthreads();   // all reads done before next prefetch overwrites this buffer
    }

    // stage accumulators through smem for the epilogue
#pragma unroll
    for (int i = 0; i < FM; i++)
#pragma unroll
        for (int j = 0; j < FN; j++)
            wmma::store_matrix_sync(sm + (size_t)(warpM * WM + i * 16) * SC + warpN * WN + j * 16,
                                    acc[i][j], SC, wmma::mem_row_major);
    __syncthreads();

    constexpr int QUADS = BM * BN / 4;
#pragma unroll 4
    for (int qd = tid; qd < QUADS; qd += THREADS) {
        const int r = qd / (BN / 4);
        const int c4 = (qd - r * (BN / 4)) * 4;
        const int m = row0 + r;
        const int n = col0 + c4;
        float4 v = *reinterpret_cast<const float4*>(sm + r * SC + c4);

        if constexpr (EPI == EPI_CONVPOS) {
            float4 bb = *reinterpret_cast<const float4*>(bias + n);
            float4 p = *reinterpret_cast<const float4*>(aux1 + (size_t)(m & (SEQ - 1)) * EMB + n);
            v.x += bb.x + p.x; v.y += bb.y + p.y; v.z += bb.z + p.z; v.w += bb.w + p.w;
            *reinterpret_cast<float4*>(C + (size_t)m * N + n) = v;
        } else if constexpr (EPI == EPI_QKV) {
            float4 bb = *reinterpret_cast<const float4*>(bias + n);
            v.x = to_tf32(v.x + bb.x); v.y = to_tf32(v.y + bb.y);
            v.z = to_tf32(v.z + bb.z); v.w = to_tf32(v.w + bb.w);
            const int which = n / EMB;               // constant within quad
            const int rr = n - which * EMB;
            const int head = rr >> 6;                // constant within quad
            const int d = rr & 63;
            const int b = m >> 10, nl = m & (SEQ - 1);
            float* dst = (which == 0) ? p0 : ((which == 1) ? p1 : p2);
            *reinterpret_cast<float4*>(dst + ((size_t)(b * NHEAD + head) * SEQ + nl) * HD + d) = v;
        } else if constexpr (EPI == EPI_SREL) {
            const float rh = aux1[((size_t)z * SEQ + m) * GRID32 + (n >> 5)];
            const float* rw = aux2 + ((size_t)z * SEQ + m) * GRID32;
            v.x = v.x * scale + rh + rw[(n + 0) & 31];
            v.y = v.y * scale + rh + rw[(n + 1) & 31];
            v.z = v.z * scale + rh + rw[(n + 2) & 31];
            v.w = v.w * scale + rh + rw[(n + 3) & 31];
            *reinterpret_cast<float4*>(C + (size_t)m * N + n) = v;
        } else if constexpr (EPI == EPI_AV) {
            const int b = z / NHEAD;
            const int head = z - b * NHEAD;
            v.x = to_tf32(v.x); v.y = to_tf32(v.y); v.z = to_tf32(v.z); v.w = to_tf32(v.w);
            *reinterpret_cast<float4*>(p0 + ((size_t)(b * SEQ + m)) * EMB + head * HD + n) = v;
        } else if constexpr (EPI == EPI_BIASRES) {
            float4 bb = *reinterpret_cast<const float4*>(bias + n);
            float4 p = *reinterpret_cast<const float4*>(aux1 + (size_t)m * N + n);
            v.x += bb.x + p.x; v.y += bb.y + p.y; v.z += bb.z + p.z; v.w += bb.w + p.w;
            *reinterpret_cast<float4*>(C + (size_t)m * N + n) = v;
        } else if constexpr (EPI == EPI_GELU) {
            float4 bb = *reinterpret_cast<const float4*>(bias + n);
            v.x = to_tf32(0.5f * (v.x + bb.x) * (1.f + erff((v.x + bb.x) * 0.70710678118654752f)));
            v.y = to_tf32(0.5f * (v.y + bb.y) * (1.f + erff((v.y + bb.y) * 0.70710678118654752f)));
            v.z = to_tf32(0.5f * (v.z + bb.z) * (1.f + erff((v.z + bb.z) * 0.70710678118654752f)));
            v.w = to_tf32(0.5f * (v.w + bb.w) * (1.f + erff((v.w + bb.w) * 0.70710678118654752f)));
            *reinterpret_cast<float4*>(C + (size_t)m * N + n) = v;
        }
    }
}

// smem bytes for a config
constexpr int wg_smem(int BM, int BN, int BK, bool BROW)
{
    int ASZ = BM * (BK + 8);
    int BSZ = BROW ? BK * (BN + 8) : BN * (BK + 8);
    return 2 * (ASZ + BSZ) * 4;
}

// ---------------- weight transpose (+tf32 round): in[K,N] -> out[N,K] ----------------
__global__ __launch_bounds__(256)
void transpose_round(const float* __restrict__ in, float* __restrict__ out, int K, int N)
{
    __shared__ float t[32][33];
    int n0 = blockIdx.x * 32, k0 = blockIdx.y * 32;
    int x = threadIdx.x, y = threadIdx.y;
#pragma unroll
    for (int i = y; i < 32; i += 8) t[i][x] = in[(size_t)(k0 + i) * N + n0 + x];
    __syncthreads();
#pragma unroll
    for (int i = y; i < 32; i += 8)
        out[(size_t)(n0 + i) * K + k0 + x] = to_tf32(t[x][i]);
}

__global__ void round_copy(const float* __restrict__ in, float* __restrict__ out, int n)
{
    int i = blockIdx.x * blockDim.x + threadIdx.x;
    if (i < n) out[i] = to_tf32(in[i]);
}

// ---------------- im2col for the 16x16/stride-16 patch conv (tf32-rounded) ----------------
__global__ void im2col_kernel(const float* __restrict__ x, float* __restrict__ col)
{
    int idx = blockIdx.x * blockDim.x + threadIdx.x;
    if (idx >= TOKENS * EMB) return;
    int m = idx / EMB, kk = idx - m * EMB;
    int b = m >> 10, p = m & 1023, ph = p >> 5, pw = p & 31;
    int c = kk >> 8, r = kk & 255, kh = r >> 4, kw = r & 15;
    col[idx] = to_tf32(x[((size_t)(b * 3 + c) * 512 + (ph * 16 + kh)) * 512 + pw * 16 + kw]);
}

// ---------------- layernorm (tf32-rounded output; feeds tf32 GEMMs only) ----------------
__device__ __forceinline__ float warpReduceSum(float v)
{
#pragma unroll
    for (int o = 16; o; o >>= 1) v += __shfl_xor_sync(0xffffffffu, v, o);
    return v;
}

__global__ __launch_bounds__(256)
void ln_kernel(const float* __restrict__ in, const float* __restrict__ w,
               const float* __restrict__ b, float* __restrict__ out)
{
    __shared__ float sh[8];
    const int row = blockIdx.x;
    const int t = threadIdx.x;
    const float* x = in + (size_t)row * EMB;
    float v0 = x[t], v1 = x[t + 256], v2 = x[t + 512];
    float s = warpReduceSum(v0 + v1 + v2);
    if ((t & 31) == 0) sh[t >> 5] = s;
    __syncthreads();
    float mean = (sh[0] + sh[1] + sh[2] + sh[3] + sh[4] + sh[5] + sh[6] + sh[7]) * (1.f / EMB);
    float d0 = v0 - mean, d1 = v1 - mean, d2 = v2 - mean;
    __syncthreads();
    float s2 = warpReduceSum(d0 * d0 + d1 * d1 + d2 * d2);
    if ((t & 31) == 0) sh[t >> 5] = s2;
    __syncthreads();
    float var = (sh[0] + sh[1] + sh[2] + sh[3] + sh[4] + sh[5] + sh[6] + sh[7]) * (1.f / EMB);
    float rstd = rsqrtf(var + 1e-5f);
    float* o = out + (size_t)row * EMB;
    o[t]       = to_tf32(d0 * rstd * w[t]       + b[t]);
    o[t + 256] = to_tf32(d1 * rstd * w[t + 256] + b[t + 256]);
    o[t + 512] = to_tf32(d2 * rstd * w[t + 512] + b[t + 512]);
}

// ---------------- decomposed rel-pos dot products ----------------
__global__ __launch_bounds__(64)
void rel_kernel(const float* __restrict__ q,
                const float* __restrict__ rph, const float* __restrict__ rpw,
                float* __restrict__ relh, float* __restrict__ relw)
{
    const int bq = blockIdx.x;
    const int p = bq & (SEQ - 1);
    const int qh = p >> 5, qw = p & 31;
    __shared__ float qs[HD];
    const int t = threadIdx.x;
    qs[t] = q[(size_t)bq * HD + t];
    __syncthreads();
    const int kidx = t & 31;
    const float* tab = (t < 32) ? (rph + (qh - kidx + 31) * HD)
                                : (rpw + (qw - kidx + 31) * HD);
    float s = 0.f;
#pragma unroll
    for (int d = 0; d < HD; d++) s = fmaf(qs[d], tab[d], s);
    if (t < 32) relh[(size_t)bq * GRID32 + kidx] = s;
    else        relw[(size_t)bq * GRID32 + kidx] = s;
}

// ---------------- row softmax over SEQ=1024 (tf32-rounded probs) ----------------
__global__ __launch_bounds__(256)
void softmax_kernel(float* __restrict__ S)
{
    __shared__ float sh[8];
    const size_t row = blockIdx.x;
    float* p = S + row * SEQ;
    const int t = threadIdx.x;
    float v0 = p[t], v1 = p[t + 256], v2 = p[t + 512], v3 = p[t + 768];
    float mx = fmaxf(fmaxf(v0, v1), fmaxf(v2, v3));
#pragma unroll
    for (int o = 16; o; o >>= 1) mx = fmaxf(mx, __shfl_xor_sync(0xffffffffu, mx, o));
    if ((t & 31) == 0) sh[t >> 5] = mx;
    __syncthreads();
    mx = fmaxf(fmaxf(fmaxf(sh[0], sh[1]), fmaxf(sh[2], sh[3])),
               fmaxf(fmaxf(sh[4], sh[5]), fmaxf(sh[6], sh[7])));
    v0 = __expf(v0 - mx); v1 = __expf(v1 - mx);
    v2 = __expf(v2 - mx); v3 = __expf(v3 - mx);
    float s = warpReduceSum(v0 + v1 + v2 + v3);
    __syncthreads();
    if ((t & 31) == 0) sh[t >> 5] = s;
    __syncthreads();
    float inv = 1.f / (sh[0] + sh[1] + sh[2] + sh[3] + sh[4] + sh[5] + sh[6] + sh[7]);
    p[t]       = to_tf32(v0 * inv);
    p[t + 256] = to_tf32(v1 * inv);
    p[t + 512] = to_tf32(v2 * inv);
    p[t + 768] = to_tf32(v3 * inv);
}

// ---------------- host orchestration ----------------
extern "C" void kernel_launch(void* const* d_in, const int* in_sizes, int n_in,
                              void* d_out, int out_size)
{
    const float* x      = (const float*)d_in[0];
    const float* conv_w = (const float*)d_in[1];
    const float* conv_b = (const float*)d_in[2];
    const float* pos    = (const float*)d_in[3];
    const float* ln1_w  = (const float*)d_in[4];
    const float* ln1_b  = (const float*)d_in[5];
    const float* qkv_w  = (const float*)d_in[6];
    const float* qkv_b  = (const float*)d_in[7];
    const float* proj_w = (const float*)d_in[8];
    const float* proj_b = (const float*)d_in[9];
    const float* rph    = (const float*)d_in[10];
    const float* rpw    = (const float*)d_in[11];
    const float* ln2_w  = (const float*)d_in[12];
    const float* ln2_b  = (const float*)d_in[13];
    const float* fc1_w  = (const float*)d_in[14];
    const float* fc1_b  = (const float*)d_in[15];
    const float* fc2_w  = (const float*)d_in[16];
    const float* fc2_b  = (const float*)d_in[17];

    float *h, *xn, *col, *q, *k, *v, *relh, *relw, *S, *attn, *mlp;
    float *cwT, *qkvT, *projT, *fc1T, *fc2T;
    cudaGetSymbolAddress((void**)&h, g_h);
    cudaGetSymbolAddress((void**)&xn, g_xn);
    cudaGetSymbolAddress((void**)&col, g_col);
    cudaGetSymbolAddress((void**)&q, g_q);
    cudaGetSymbolAddress((void**)&k, g_k);
    cudaGetSymbolAddress((void**)&v, g_v);
    cudaGetSymbolAddress((void**)&relh, g_relh);
    cudaGetSymbolAddress((void**)&relw, g_relw);
    cudaGetSymbolAddress((void**)&S, g_S);
    cudaGetSymbolAddress((void**)&attn, g_attn);
    cudaGetSymbolAddress((void**)&mlp, g_mlp);
    cudaGetSymbolAddress((void**)&cwT, g_cwT);
    cudaGetSymbolAddress((void**)&qkvT, g_qkvT);
    cudaGetSymbolAddress((void**)&projT, g_projT);
    cudaGetSymbolAddress((void**)&fc1T, g_fc1T);
    cudaGetSymbolAddress((void**)&fc2T, g_fc2T);

    // big-tile config: 128x128x32, warp tile 64x32 (8 warps / 256 thr)
    constexpr int SM_BIG = wg_smem(128, 128, 32, false);   // 81920 B
    constexpr int SM_AV  = wg_smem(128, 64, 32, true);     // 59392 B

    cudaFuncSetAttribute((const void*)wgemm<128,128,32,64,32,EPI_CONVPOS,false>,
                         cudaFuncAttributeMaxDynamicSharedMemorySize, SM_BIG);
    cudaFuncSetAttribute((const void*)wgemm<128,128,32,64,32,EPI_QKV,false>,
                         cudaFuncAttributeMaxDynamicSharedMemorySize, SM_BIG);
    cudaFuncSetAttribute((const void*)wgemm<128,128,32,64,32,EPI_SREL,false>,
                         cudaFuncAttributeMaxDynamicSharedMemorySize, SM_BIG);
    cudaFuncSetAttribute((const void*)wgemm<128,64,32,32,32,EPI_AV,true>,
                         cudaFuncAttributeMaxDynamicSharedMemorySize, SM_AV);
    cudaFuncSetAttribute((const void*)wgemm<128,128,32,64,32,EPI_BIASRES,false>,
                         cudaFuncAttributeMaxDynamicSharedMemorySize, SM_BIG);
    cudaFuncSetAttribute((const void*)wgemm<128,128,32,64,32,EPI_GELU,false>,
                         cudaFuncAttributeMaxDynamicSharedMemorySize, SM_BIG);

    const float scale = 0.125f;  // HD^-0.5
    const dim3 tb(32, 8);

    // weight prep: [K,N] -> [N,K] with tf32 rounding
    round_copy<<<(EMB * EMB + 255) / 256, 256>>>(conv_w, cwT, EMB * EMB);
    for (int i = 0; i < 4; i++) {
        transpose_round<<<dim3(3 * EMB / 32, EMB / 32), tb>>>(
            qkv_w + (size_t)i * EMB * 3 * EMB, qkvT + (size_t)i * 3 * EMB * EMB, EMB, 3 * EMB);
        transpose_round<<<dim3(EMB / 32, EMB / 32), tb>>>(
            proj_w + (size_t)i * EMB * EMB, projT + (size_t)i * EMB * EMB, EMB, EMB);
        transpose_round<<<dim3(MLPD / 32, EMB / 32), tb>>>(
            fc1_w + (size_t)i * EMB * MLPD, fc1T + (size_t)i * MLPD * EMB, EMB, MLPD);
        transpose_round<<<dim3(EMB / 32, MLPD / 32), tb>>>(
            fc2_w + (size_t)i * MLPD * EMB, fc2T + (size_t)i * EMB * MLPD, MLPD, EMB);
    }

    // patch embed: im2col + GEMM + conv_b + pos_embed
    im2col_kernel<<<(TOKENS * EMB + 255) / 256, 256>>>(x, col);
    wgemm<128,128,32,64,32,EPI_CONVPOS,false><<<dim3(EMB/128, TOKENS/128), 256, SM_BIG>>>(
        col, cwT, h, EMB, EMB, 0, 0, 0,
        conv_b, pos, nullptr, nullptr, nullptr, nullptr, 0.f);

    for (int i = 0; i < 4; i++) {
        ln_kernel<<<TOKENS, 256>>>(h, ln1_w + i * EMB, ln1_b + i * EMB, xn);

        wgemm<128,128,32,64,32,EPI_QKV,false><<<dim3(3*EMB/128, TOKENS/128), 256, SM_BIG>>>(
            xn, qkvT + (size_t)i * 3 * EMB * EMB, nullptr, 3 * EMB, EMB, 0, 0, 0,
            qkv_b + (size_t)i * 3 * EMB, nullptr, nullptr, q, k, v, 0.f);

        rel_kernel<<<BHEADS * SEQ, 64>>>(q, rph + (size_t)i * 63 * HD, rpw + (size_t)i * 63 * HD,
                                         relh, relw);

        // S = scale * q @ k^T + rel_h + rel_w  (batched over 48 bh)
        wgemm<128,128,32,64,32,EPI_SREL,false><<<dim3(SEQ/128, SEQ/128, BHEADS), 256, SM_BIG>>>(
            q, k, S, SEQ, HD,
            (size_t)SEQ * HD, (size_t)SEQ * HD, (size_t)SEQ * SEQ,
            nullptr, relh, relw, nullptr, nullptr, nullptr, scale);

        softmax_kernel<<<BHEADS * SEQ, 256>>>(S);

        // O = P @ v  (B row-major [K,N])
        wgemm<128,64,32,32,32,EPI_AV,true><<<dim3(1, SEQ/128, BHEADS), 256, SM_AV>>>(
            S, v, nullptr, HD, SEQ,
            (size_t)SEQ * SEQ, (size_t)SEQ * HD, 0,
            nullptr, nullptr, nullptr, attn, nullptr, nullptr, 0.f);

        wgemm<128,128,32,64,32,EPI_BIASRES,false><<<dim3(EMB/128, TOKENS/128), 256, SM_BIG>>>(
            attn, projT + (size_t)i * EMB * EMB, h, EMB, EMB, 0, 0, 0,
            proj_b + (size_t)i * EMB, h, nullptr, nullptr, nullptr, nullptr, 0.f);

        ln_kernel<<<TOKENS, 256>>>(h, ln2_w + i * EMB, ln2_b + i * EMB, xn);

        wgemm<128,128,32,64,32,EPI_GELU,false><<<dim3(MLPD/128, TOKENS/128), 256, SM_BIG>>>(
            xn, fc1T + (size_t)i * MLPD * EMB, mlp, MLPD, EMB, 0, 0, 0,
            fc1_b + (size_t)i * MLPD, nullptr, nullptr, nullptr, nullptr, nullptr, 0.f);

        float* dst = (i == 3) ? (float*)d_out : h;
        wgemm<128,128,32,64,32,EPI_BIASRES,false><<<dim3(EMB/128, TOKENS/128), 256, SM_BIG>>>(
            mlp, fc2T + (size_t)i * EMB * MLPD, dst, EMB, MLPD, 0, 0, 0,
            fc2_b + (size_t)i * EMB, h, nullptr, nullptr, nullptr, nullptr, 0.f);
    }
}

// round 10
// speedup vs baseline: 1.9233x; 1.2410x over previous
#include <cuda_runtime.h>
#include <cuda_bf16.h>
#include <math.h>
#include <stdint.h>
#include <mma.h>

using namespace nvcuda;

// ---------------- problem constants ----------------
#define TOKENS 4096      // B(4) * 32 * 32
#define EMB    768
#define NHEAD  12
#define HD     64
#define SEQ    1024      // tokens per image
#define BHEADS 48        // B * NHEAD
#define MLPD   3072
#define GRID32 32

typedef __nv_bfloat16 bf16;

// ---------------- scratch (device globals; no allocs allowed) ----------------
__device__ float g_h[TOKENS * EMB];
__device__ float g_relh[BHEADS * SEQ * GRID32];
__device__ float g_relw[BHEADS * SEQ * GRID32];
__device__ float g_S[(size_t)BHEADS * SEQ * SEQ];   // 201 MB; softmax rewrites rows as bf16 hi/lo planes

// activation hi/lo planes
__device__ bf16 g_colH[TOKENS * EMB],  g_colL[TOKENS * EMB];
__device__ bf16 g_xnH[TOKENS * EMB],   g_xnL[TOKENS * EMB];
__device__ bf16 g_qH[BHEADS * SEQ * HD], g_qL[BHEADS * SEQ * HD];
__device__ bf16 g_kH[BHEADS * SEQ * HD], g_kL[BHEADS * SEQ * HD];
__device__ bf16 g_vH[BHEADS * SEQ * HD], g_vL[BHEADS * SEQ * HD];
__device__ bf16 g_attnH[TOKENS * EMB], g_attnL[TOKENS * EMB];
__device__ bf16 g_mlpH[TOKENS * MLPD], g_mlpL[TOKENS * MLPD];

// weight hi/lo planes, [N,K] K-major
__device__ bf16 g_cwTH[EMB * EMB],              g_cwTL[EMB * EMB];
__device__ bf16 g_qkvTH[4 * 3 * EMB * EMB],     g_qkvTL[4 * 3 * EMB * EMB];
__device__ bf16 g_projTH[4 * EMB * EMB],        g_projTL[4 * EMB * EMB];
__device__ bf16 g_fc1TH[4 * MLPD * EMB],        g_fc1TL[4 * MLPD * EMB];
__device__ bf16 g_fc2TH[4 * EMB * MLPD],        g_fc2TL[4 * EMB * MLPD];

enum { EPI_CONVPOS = 1, EPI_QKV = 2, EPI_SREL = 3, EPI_AV = 4, EPI_BIASRES = 5, EPI_GELU = 6 };

// ---------------- helpers ----------------
__device__ __forceinline__ void split1(float x, bf16& h, bf16& l)
{
    h = __float2bfloat16(x);
    l = __float2bfloat16(x - __bfloat162float(h));
}

__device__ __forceinline__ void split_store4(float4 v, bf16* ph, bf16* pl)
{
    bf16 h0, h1, h2, h3, l0, l1, l2, l3;
    split1(v.x, h0, l0); split1(v.y, h1, l1);
    split1(v.z, h2, l2); split1(v.w, h3, l3);
    __nv_bfloat162 a, b;
    a.x = h0; a.y = h1; b.x = h2; b.y = h3;
    reinterpret_cast<__nv_bfloat162*>(ph)[0] = a;
    reinterpret_cast<__nv_bfloat162*>(ph)[1] = b;
    a.x = l0; a.y = l1; b.x = l2; b.y = l3;
    reinterpret_cast<__nv_bfloat162*>(pl)[0] = a;
    reinterpret_cast<__nv_bfloat162*>(pl)[1] = b;
}

__device__ __forceinline__ uint32_t smem_u32(const void* p)
{
    return (uint32_t)__cvta_generic_to_shared(p);
}

__device__ __forceinline__ void cp16(uint32_t dst, const void* src)
{
    asm volatile("cp.async.cg.shared.global [%0], [%1], 16;\n" :: "r"(dst), "l"(src));
}
__device__ __forceinline__ void cp_commit()
{
    asm volatile("cp.async.commit_group;\n" ::: "memory");
}
template <int N>
__device__ __forceinline__ void cp_wait()
{
    asm volatile("cp.async.wait_group %0;\n" :: "n"(N) : "memory");
}

// stage NROWS x CFL bf16 from global (row stride ld halves) into smem (row stride ss halves)
template <int NROWS, int CFL, int THREADS>
__device__ __forceinline__ void ld_tile_h(const bf16* __restrict__ g, int ld,
                                          bf16* __restrict__ s, int ss, int tid)
{
    constexpr int CH = NROWS * (CFL / 8);      // 16-byte chunks
    static_assert(CH % THREADS == 0, "chunk mapping");
#pragma unroll
    for (int i = 0; i < CH / THREADS; i++) {
        int lin = i * THREADS + tid;
        int r = lin / (CFL / 8);
        int c = (lin - r * (CFL / 8)) * 8;
        cp16(smem_u32(s + r * ss + c), g + (size_t)r * ld + c);
    }
}

// ---------------- split-bf16 wmma GEMM with fused epilogues ----------------
// C = (AH+AL) @ (BH+BL)^T', dropping AL*BL. A: [M,K] row-major planes.
// BROW=false: B planes are [N,K] row-major (wmma col_major). BROW=true: [K,N] row-major.
template <int BM, int BN, int BK, int WM, int WN, int EPI, bool BROW>
__global__ __launch_bounds__((BM / WM) * (BN / WN) * 32)
void wgemm(const bf16* __restrict__ AH, const bf16* __restrict__ AL, int ldA,
           const bf16* __restrict__ BH, const bf16* __restrict__ BL, int ldB,
           float* __restrict__ C, int N, int K,
           size_t sAs, size_t sBs, size_t sCs,
           const float* __restrict__ bias,
           const float* __restrict__ aux1, const float* __restrict__ aux2,
           bf16* __restrict__ o0h, bf16* __restrict__ o0l,
           bf16* __restrict__ o1h, bf16* __restrict__ o1l,
           bf16* __restrict__ o2h, bf16* __restrict__ o2l,
           float scale)
{
    constexpr int WARPS_M = BM / WM;
    constexpr int WARPS_N = BN / WN;
    constexpr int THREADS = WARPS_M * WARPS_N * 32;
    constexpr int FM = WM / 16, FN = WN / 16;
    constexpr int SA = BK + 8;                     // halves
    constexpr int SB = BROW ? (BN + 8) : (BK + 8);
    constexpr int BROWS = BROW ? BK : BN;
    constexpr int ASZ = BM * SA;                   // halves per plane
    constexpr int BSZ = BROWS * SB;
    constexpr int STAGE = 2 * (ASZ + BSZ);         // halves (hi+lo planes)
    constexpr int SC = BN + 8;                     // C staging stride (floats)
    static_assert(BM * SC * 2 <= 2 * STAGE, "C staging fits");

    extern __shared__ bf16 smh[];

    const int z = blockIdx.z;
    AH += (size_t)z * sAs; AL += (size_t)z * sAs;
    BH += (size_t)z * sBs; BL += (size_t)z * sBs;
    if (C) C += (size_t)z * sCs;

    const int tid = threadIdx.x;
    const int wid = tid >> 5;
    const int warpM = wid % WARPS_M;
    const int warpN = wid / WARPS_M;
    const int row0 = blockIdx.y * BM;
    const int col0 = blockIdx.x * BN;

    wmma::fragment<wmma::accumulator, 16, 16, 16, float> acc[FM][FN];
#pragma unroll
    for (int i = 0; i < FM; i++)
#pragma unroll
        for (int j = 0; j < FN; j++) wmma::fill_fragment(acc[i][j], 0.f);

    const int KB = K / BK;

    // stage loader
    auto stage_in = [&](int kb, int buf) {
        bf16* st = smh + buf * STAGE;
        ld_tile_h<BM, BK, THREADS>(AH + (size_t)row0 * ldA + kb * BK, ldA, st, SA, tid);
        ld_tile_h<BM, BK, THREADS>(AL + (size_t)row0 * ldA + kb * BK, ldA, st + ASZ, SA, tid);
        if constexpr (BROW) {
            ld_tile_h<BK, BN, THREADS>(BH + (size_t)kb * BK * ldB + col0, ldB, st + 2 * ASZ, SB, tid);
            ld_tile_h<BK, BN, THREADS>(BL + (size_t)kb * BK * ldB + col0, ldB, st + 2 * ASZ + BSZ, SB, tid);
        } else {
            ld_tile_h<BN, BK, THREADS>(BH + (size_t)col0 * ldB + kb * BK, ldB, st + 2 * ASZ, SB, tid);
            ld_tile_h<BN, BK, THREADS>(BL + (size_t)col0 * ldB + kb * BK, ldB, st + 2 * ASZ + BSZ, SB, tid);
        }
    };

    stage_in(0, 0);
    cp_commit();

    for (int kb = 0; kb < KB; kb++) {
        if (kb + 1 < KB) stage_in(kb + 1, (kb + 1) & 1);
        cp_commit();
        cp_wait<1>();
        __syncthreads();

        const bf16* st = smh + (kb & 1) * STAGE;
        const bf16* AHt = st;
        const bf16* ALt = st + ASZ;
        const bf16* BHt = st + 2 * ASZ;
        const bf16* BLt = st + 2 * ASZ + BSZ;

#pragma unroll
        for (int kk = 0; kk < BK / 16; kk++) {
            wmma::fragment<wmma::matrix_a, 16, 16, 16, bf16, wmma::row_major> ah[FM], al[FM];
#pragma unroll
            for (int i = 0; i < FM; i++) {
                wmma::load_matrix_sync(ah[i], AHt + (warpM * WM + i * 16) * SA + kk * 16, SA);
                wmma::load_matrix_sync(al[i], ALt + (warpM * WM + i * 16) * SA + kk * 16, SA);
            }
            if constexpr (BROW) {
                wmma::fragment<wmma::matrix_b, 16, 16, 16, bf16, wmma::row_major> bh[FN], bl[FN];
#pragma unroll
                for (int j = 0; j < FN; j++) {
                    wmma::load_matrix_sync(bh[j], BHt + kk * 16 * SB + warpN * WN + j * 16, SB);
                    wmma::load_matrix_sync(bl[j], BLt + kk * 16 * SB + warpN * WN + j * 16, SB);
                }
#pragma unroll
                for (int i = 0; i < FM; i++)
#pragma unroll
                    for (int j = 0; j < FN; j++) {
                        wmma::mma_sync(acc[i][j], ah[i], bh[j], acc[i][j]);
                        wmma::mma_sync(acc[i][j], ah[i], bl[j], acc[i][j]);
                        wmma::mma_sync(acc[i][j], al[i], bh[j], acc[i][j]);
                    }
            } else {
                wmma::fragment<wmma::matrix_b, 16, 16, 16, bf16, wmma::col_major> bh[FN], bl[FN];
#pragma unroll
                for (int j = 0; j < FN; j++) {
                    wmma::load_matrix_sync(bh[j], BHt + (warpN * WN + j * 16) * SB + kk * 16, SB);
                    wmma::load_matrix_sync(bl[j], BLt + (warpN * WN + j * 16) * SB + kk * 16, SB);
                }
#pragma unroll
                for (int i = 0; i < FM; i++)
#pragma unroll
                    for (int j = 0; j < FN; j++) {
                        wmma::mma_sync(acc[i][j], ah[i], bh[j], acc[i][j]);
                        wmma::mma_sync(acc[i][j], ah[i], bl[j], acc[i][j]);
                        wmma::mma_sync(acc[i][j], al[i], bh[j], acc[i][j]);
                    }
            }
        }
        __syncthreads();
    }

    // stage accumulators through smem for the epilogue
    float* smf = reinterpret_cast<float*>(smh);
#pragma unroll
    for (int i = 0; i < FM; i++)
#pragma unroll
        for (int j = 0; j < FN; j++)
            wmma::store_matrix_sync(smf + (size_t)(warpM * WM + i * 16) * SC + warpN * WN + j * 16,
                                    acc[i][j], SC, wmma::mem_row_major);
    __syncthreads();

    constexpr int QUADS = BM * BN / 4;
#pragma unroll 4
    for (int qd = tid; qd < QUADS; qd += THREADS) {
        const int r = qd / (BN / 4);
        const int c4 = (qd - r * (BN / 4)) * 4;
        const int m = row0 + r;
        const int n = col0 + c4;
        float4 v = *reinterpret_cast<const float4*>(smf + r * SC + c4);

        if constexpr (EPI == EPI_CONVPOS) {
            float4 bb = *reinterpret_cast<const float4*>(bias + n);
            float4 p = *reinterpret_cast<const float4*>(aux1 + (size_t)(m & (SEQ - 1)) * EMB + n);
            v.x += bb.x + p.x; v.y += bb.y + p.y; v.z += bb.z + p.z; v.w += bb.w + p.w;
            *reinterpret_cast<float4*>(C + (size_t)m * N + n) = v;
        } else if constexpr (EPI == EPI_QKV) {
            float4 bb = *reinterpret_cast<const float4*>(bias + n);
            v.x += bb.x; v.y += bb.y; v.z += bb.z; v.w += bb.w;
            const int which = n / EMB;
            const int rr = n - which * EMB;
            const int head = rr >> 6;
            const int d = rr & 63;
            const int b = m >> 10, nl = m & (SEQ - 1);
            bf16* dh = (which == 0) ? o0h : ((which == 1) ? o1h : o2h);
            bf16* dl = (which == 0) ? o0l : ((which == 1) ? o1l : o2l);
            size_t off = ((size_t)(b * NHEAD + head) * SEQ + nl) * HD + d;
            split_store4(v, dh + off, dl + off);
        } else if constexpr (EPI == EPI_SREL) {
            const float rh = aux1[((size_t)z * SEQ + m) * GRID32 + (n >> 5)];
            const float* rw = aux2 + ((size_t)z * SEQ + m) * GRID32;
            v.x = v.x * scale + rh + rw[(n + 0) & 31];
            v.y = v.y * scale + rh + rw[(n + 1) & 31];
            v.z = v.z * scale + rh + rw[(n + 2) & 31];
            v.w = v.w * scale + rh + rw[(n + 3) & 31];
            *reinterpret_cast<float4*>(C + (size_t)m * N + n) = v;
        } else if constexpr (EPI == EPI_AV) {
            const int b = z / NHEAD;
            const int head = z - b * NHEAD;
            size_t off = ((size_t)(b * SEQ + m)) * EMB + head * HD + n;
            split_store4(v, o0h + off, o0l + off);
        } else if constexpr (EPI == EPI_BIASRES) {
            float4 bb = *reinterpret_cast<const float4*>(bias + n);
            float4 p = *reinterpret_cast<const float4*>(aux1 + (size_t)m * N + n);
            v.x += bb.x + p.x; v.y += bb.y + p.y; v.z += bb.z + p.z; v.w += bb.w + p.w;
            *reinterpret_cast<float4*>(C + (size_t)m * N + n) = v;
        } else if constexpr (EPI == EPI_GELU) {
            float4 bb = *reinterpret_cast<const float4*>(bias + n);
            v.x = 0.5f * (v.x + bb.x) * (1.f + erff((v.x + bb.x) * 0.70710678118654752f));
            v.y = 0.5f * (v.y + bb.y) * (1.f + erff((v.y + bb.y) * 0.70710678118654752f));
            v.z = 0.5f * (v.z + bb.z) * (1.f + erff((v.z + bb.z) * 0.70710678118654752f));
            v.w = 0.5f * (v.w + bb.w) * (1.f + erff((v.w + bb.w) * 0.70710678118654752f));
            split_store4(v, o0h + (size_t)m * N + n, o0l + (size_t)m * N + n);
        }
    }
}

constexpr int wg_smem_bytes(int BM, int BN, int BK, bool BROW)
{
    int ASZ = BM * (BK + 8);
    int BROWS = BROW ? BK : BN;
    int SB = BROW ? (BN + 8) : (BK + 8);
    int BSZ = BROWS * SB;
    return 2 /*stages*/ * 2 /*planes*/ * (ASZ + BSZ) * 2 /*bytes*/;
}

// ---------------- weight prep: split(+transpose) fp32 -> bf16 hi/lo [N,K] ----------------
struct PrepJob {
    const float* src;
    bf16* dh;
    bf16* dl;
    int K;
    int N;
    int trans;   // 1: src [K,N] -> out [N,K]; 0: src already [N,K]
};
struct Jobs8 { PrepJob j[8]; };

__global__ __launch_bounds__(256)
void prep_kernel(Jobs8 jobs)
{
    const PrepJob jb = jobs.j[blockIdx.z];
    __shared__ float t[32][33];
    const int x = threadIdx.x, y = threadIdx.y;
    if (jb.trans) {
        const int n0 = blockIdx.x * 32, k0 = blockIdx.y * 32;
        if (n0 >= jb.N || k0 >= jb.K) return;
#pragma unroll
        for (int i = y; i < 32; i += 8) t[i][x] = jb.src[(size_t)(k0 + i) * jb.N + n0 + x];
        __syncthreads();
#pragma unroll
        for (int i = y; i < 32; i += 8) {
            bf16 h, l;
            split1(t[x][i], h, l);
            size_t o = (size_t)(n0 + i) * jb.K + k0 + x;
            jb.dh[o] = h; jb.dl[o] = l;
        }
    } else {
        const int k0 = blockIdx.x * 32, n0 = blockIdx.y * 32;
        if (k0 >= jb.K || n0 >= jb.N) return;
#pragma unroll
        for (int i = y; i < 32; i += 8) {
            size_t o = (size_t)(n0 + i) * jb.K + k0 + x;
            bf16 h, l;
            split1(jb.src[o], h, l);
            jb.dh[o] = h; jb.dl[o] = l;
        }
    }
}

// ---------------- im2col (split output) ----------------
__global__ void im2col_kernel(const float* __restrict__ x,
                              bf16* __restrict__ colH, bf16* __restrict__ colL)
{
    int idx = blockIdx.x * blockDim.x + threadIdx.x;
    if (idx >= TOKENS * EMB) return;
    int m = idx / EMB, kk = idx - m * EMB;
    int b = m >> 10, p = m & 1023, ph = p >> 5, pw = p & 31;
    int c = kk >> 8, r = kk & 255, kh = r >> 4, kw = r & 15;
    float v = x[((size_t)(b * 3 + c) * 512 + (ph * 16 + kh)) * 512 + pw * 16 + kw];
    bf16 h, l;
    split1(v, h, l);
    colH[idx] = h; colL[idx] = l;
}

// ---------------- layernorm (split output planes) ----------------
__device__ __forceinline__ float warpReduceSum(float v)
{
#pragma unroll
    for (int o = 16; o; o >>= 1) v += __shfl_xor_sync(0xffffffffu, v, o);
    return v;
}

__global__ __launch_bounds__(256)
void ln_kernel(const float* __restrict__ in, const float* __restrict__ w,
               const float* __restrict__ b,
               bf16* __restrict__ outH, bf16* __restrict__ outL)
{
    __shared__ float sh[8];
    const int row = blockIdx.x;
    const int t = threadIdx.x;
    const float* x = in + (size_t)row * EMB;
    float v0 = x[t], v1 = x[t + 256], v2 = x[t + 512];
    float s = warpReduceSum(v0 + v1 + v2);
    if ((t & 31) == 0) sh[t >> 5] = s;
    __syncthreads();
    float mean = (sh[0] + sh[1] + sh[2] + sh[3] + sh[4] + sh[5] + sh[6] + sh[7]) * (1.f / EMB);
    float d0 = v0 - mean, d1 = v1 - mean, d2 = v2 - mean;
    __syncthreads();
    float s2 = warpReduceSum(d0 * d0 + d1 * d1 + d2 * d2);
    if ((t & 31) == 0) sh[t >> 5] = s2;
    __syncthreads();
    float var = (sh[0] + sh[1] + sh[2] + sh[3] + sh[4] + sh[5] + sh[6] + sh[7]) * (1.f / EMB);
    float rstd = rsqrtf(var + 1e-5f);
    bf16 h, l;
    size_t base = (size_t)row * EMB;
    float o0 = d0 * rstd * w[t] + b[t];
    float o1 = d1 * rstd * w[t + 256] + b[t + 256];
    float o2 = d2 * rstd * w[t + 512] + b[t + 512];
    split1(o0, h, l); outH[base + t] = h;       outL[base + t] = l;
    split1(o1, h, l); outH[base + t + 256] = h; outL[base + t + 256] = l;
    split1(o2, h, l); outH[base + t + 512] = h; outL[base + t + 512] = l;
}

// ---------------- decomposed rel-pos dot products (q reconstructed from planes) ----------------
__global__ __launch_bounds__(64)
void rel_kernel(const bf16* __restrict__ qH, const bf16* __restrict__ qL,
                const float* __restrict__ rph, const float* __restrict__ rpw,
                float* __restrict__ relh, float* __restrict__ relw)
{
    const int bq = blockIdx.x;
    const int p = bq & (SEQ - 1);
    const int qh = p >> 5, qw = p & 31;
    __shared__ float qs[HD];
    const int t = threadIdx.x;
    qs[t] = __bfloat162float(qH[(size_t)bq * HD + t]) + __bfloat162float(qL[(size_t)bq * HD + t]);
    __syncthreads();
    const int kidx = t & 31;
    const float* tab = (t < 32) ? (rph + (qh - kidx + 31) * HD)
                                : (rpw + (qw - kidx + 31) * HD);
    float s = 0.f;
#pragma unroll
    for (int d = 0; d < HD; d++) s = fmaf(qs[d], tab[d], s);
    if (t < 32) relh[(size_t)bq * GRID32 + kidx] = s;
    else        relw[(size_t)bq * GRID32 + kidx] = s;
}

// ---------------- row softmax over SEQ=1024, writes split planes in place ----------------
__global__ __launch_bounds__(256)
void softmax_kernel(float* __restrict__ S)
{
    __shared__ float sh[8];
    const size_t row = blockIdx.x;
    float* p = S + row * SEQ;
    const int t = threadIdx.x;
    float v0 = p[t], v1 = p[t + 256], v2 = p[t + 512], v3 = p[t + 768];
    float mx = fmaxf(fmaxf(v0, v1), fmaxf(v2, v3));
#pragma unroll
    for (int o = 16; o; o >>= 1) mx = fmaxf(mx, __shfl_xor_sync(0xffffffffu, mx, o));
    if ((t & 31) == 0) sh[t >> 5] = mx;
    __syncthreads();
    mx = fmaxf(fmaxf(fmaxf(sh[0], sh[1]), fmaxf(sh[2], sh[3])),
               fmaxf(fmaxf(sh[4], sh[5]), fmaxf(sh[6], sh[7])));
    v0 = __expf(v0 - mx); v1 = __expf(v1 - mx);
    v2 = __expf(v2 - mx); v3 = __expf(v3 - mx);
    float s = warpReduceSum(v0 + v1 + v2 + v3);
    __syncthreads();
    if ((t & 31) == 0) sh[t >> 5] = s;
    __syncthreads();
    float inv = 1.f / (sh[0] + sh[1] + sh[2] + sh[3] + sh[4] + sh[5] + sh[6] + sh[7]);
    // rewrite row as bf16 planes: [0,1024) hi, [1024,2048) lo (same 4 KB)
    bf16* ph = reinterpret_cast<bf16*>(p);
    bf16* pl = ph + SEQ;
    bf16 h, l;
    split1(v0 * inv, h, l); ph[t] = h;       pl[t] = l;
    split1(v1 * inv, h, l); ph[t + 256] = h; pl[t + 256] = l;
    split1(v2 * inv, h, l); ph[t + 512] = h; pl[t + 512] = l;
    split1(v3 * inv, h, l); ph[t + 768] = h; pl[t + 768] = l;
}

// ---------------- host orchestration ----------------
extern "C" void kernel_launch(void* const* d_in, const int* in_sizes, int n_in,
                              void* d_out, int out_size)
{
    const float* x      = (const float*)d_in[0];
    const float* conv_w = (const float*)d_in[1];
    const float* conv_b = (const float*)d_in[2];
    const float* pos    = (const float*)d_in[3];
    const float* ln1_w  = (const float*)d_in[4];
    const float* ln1_b  = (const float*)d_in[5];
    const float* qkv_w  = (const float*)d_in[6];
    const float* qkv_b  = (const float*)d_in[7];
    const float* proj_w = (const float*)d_in[8];
    const float* proj_b = (const float*)d_in[9];
    const float* rph    = (const float*)d_in[10];
    const float* rpw    = (const float*)d_in[11];
    const float* ln2_w  = (const float*)d_in[12];
    const float* ln2_b  = (const float*)d_in[13];
    const float* fc1_w  = (const float*)d_in[14];
    const float* fc1_b  = (const float*)d_in[15];
    const float* fc2_w  = (const float*)d_in[16];
    const float* fc2_b  = (const float*)d_in[17];

    float *h, *relh, *relw, *S;
    bf16 *colH, *colL, *xnH, *xnL, *qH, *qL, *kH, *kL, *vH, *vL, *attnH, *attnL, *mlpH, *mlpL;
    bf16 *cwTH, *cwTL, *qkvTH, *qkvTL, *projTH, *projTL, *fc1TH, *fc1TL, *fc2TH, *fc2TL;
    cudaGetSymbolAddress((void**)&h, g_h);
    cudaGetSymbolAddress((void**)&relh, g_relh);
    cudaGetSymbolAddress((void**)&relw, g_relw);
    cudaGetSymbolAddress((void**)&S, g_S);
    cudaGetSymbolAddress((void**)&colH, g_colH);   cudaGetSymbolAddress((void**)&colL, g_colL);
    cudaGetSymbolAddress((void**)&xnH, g_xnH);     cudaGetSymbolAddress((void**)&xnL, g_xnL);
    cudaGetSymbolAddress((void**)&qH, g_qH);       cudaGetSymbolAddress((void**)&qL, g_qL);
    cudaGetSymbolAddress((void**)&kH, g_kH);       cudaGetSymbolAddress((void**)&kL, g_kL);
    cudaGetSymbolAddress((void**)&vH, g_vH);       cudaGetSymbolAddress((void**)&vL, g_vL);
    cudaGetSymbolAddress((void**)&attnH, g_attnH); cudaGetSymbolAddress((void**)&attnL, g_attnL);
    cudaGetSymbolAddress((void**)&mlpH, g_mlpH);   cudaGetSymbolAddress((void**)&mlpL, g_mlpL);
    cudaGetSymbolAddress((void**)&cwTH, g_cwTH);   cudaGetSymbolAddress((void**)&cwTL, g_cwTL);
    cudaGetSymbolAddress((void**)&qkvTH, g_qkvTH); cudaGetSymbolAddress((void**)&qkvTL, g_qkvTL);
    cudaGetSymbolAddress((void**)&projTH, g_projTH); cudaGetSymbolAddress((void**)&projTL, g_projTL);
    cudaGetSymbolAddress((void**)&fc1TH, g_fc1TH); cudaGetSymbolAddress((void**)&fc1TL, g_fc1TL);
    cudaGetSymbolAddress((void**)&fc2TH, g_fc2TH); cudaGetSymbolAddress((void**)&fc2TL, g_fc2TL);

    constexpr int SM_BIG = wg_smem_bytes(128, 128, 64, false);   // 147456
    constexpr int SM_AV  = wg_smem_bytes(128, 64, 64, true);     // 110592

    cudaFuncSetAttribute((const void*)wgemm<128,128,64,64,32,EPI_CONVPOS,false>,
                         cudaFuncAttributeMaxDynamicSharedMemorySize, SM_BIG);
    cudaFuncSetAttribute((const void*)wgemm<128,128,64,64,32,EPI_QKV,false>,
                         cudaFuncAttributeMaxDynamicSharedMemorySize, SM_BIG);
    cudaFuncSetAttribute((const void*)wgemm<128,128,64,64,32,EPI_SREL,false>,
                         cudaFuncAttributeMaxDynamicSharedMemorySize, SM_BIG);
    cudaFuncSetAttribute((const void*)wgemm<128,64,64,32,32,EPI_AV,true>,
                         cudaFuncAttributeMaxDynamicSharedMemorySize, SM_AV);
    cudaFuncSetAttribute((const void*)wgemm<128,128,64,64,32,EPI_BIASRES,false>,
                         cudaFuncAttributeMaxDynamicSharedMemorySize, SM_BIG);
    cudaFuncSetAttribute((const void*)wgemm<128,128,64,64,32,EPI_GELU,false>,
                         cudaFuncAttributeMaxDynamicSharedMemorySize, SM_BIG);

    const float scale = 0.125f;  // HD^-0.5
    const dim3 tb(32, 8);

    // ---- weight prep (4 launches; ordering keeps launch #6 = conv wgemm for ncu) ----
    {   // launch 1: qkv + proj transposes (8 jobs)
        Jobs8 J{};
        for (int l = 0; l < 4; l++) {
            J.j[l]     = { qkv_w  + (size_t)l * EMB * 3 * EMB,
                           qkvTH  + (size_t)l * 3 * EMB * EMB,
                           qkvTL  + (size_t)l * 3 * EMB * EMB, EMB, 3 * EMB, 1 };
            J.j[4 + l] = { proj_w + (size_t)l * EMB * EMB,
                           projTH + (size_t)l * EMB * EMB,
                           projTL + (size_t)l * EMB * EMB, EMB, EMB, 1 };
        }
        prep_kernel<<<dim3(3 * EMB / 32, EMB / 32, 8), tb>>>(J);
    }
    {   // launch 2: fc1 transposes
        Jobs8 J{};
        for (int l = 0; l < 4; l++)
            J.j[l] = { fc1_w + (size_t)l * EMB * MLPD,
                       fc1TH + (size_t)l * MLPD * EMB,
                       fc1TL + (size_t)l * MLPD * EMB, EMB, MLPD, 1 };
        prep_kernel<<<dim3(MLPD / 32, EMB / 32, 4), tb>>>(J);
    }
    {   // launch 3: fc2 transposes
        Jobs8 J{};
        for (int l = 0; l < 4; l++)
            J.j[l] = { fc2_w + (size_t)l * MLPD * EMB,
                       fc2TH + (size_t)l * EMB * MLPD,
                       fc2TL + (size_t)l * EMB * MLPD, MLPD, EMB, 1 };
        prep_kernel<<<dim3(EMB / 32, MLPD / 32, 4), tb>>>(J);
    }
    {   // launch 4: conv split (already [N,K])
        Jobs8 J{};
        J.j[0] = { conv_w, cwTH, cwTL, EMB, EMB, 0 };
        prep_kernel<<<dim3(EMB / 32, EMB / 32, 1), tb>>>(J);
    }

    // launch 5: im2col
    im2col_kernel<<<(TOKENS * EMB + 255) / 256, 256>>>(x, colH, colL);

    // launch 6: patch-embed GEMM (+conv_b +pos)  <- ncu -s 5 -c 1 captures this
    wgemm<128,128,64,64,32,EPI_CONVPOS,false><<<dim3(EMB/128, TOKENS/128), 256, SM_BIG>>>(
        colH, colL, EMB, cwTH, cwTL, EMB, h, EMB, EMB, 0, 0, 0,
        conv_b, pos, nullptr, nullptr, nullptr, nullptr, nullptr, nullptr, nullptr, 0.f);

    for (int i = 0; i < 4; i++) {
        ln_kernel<<<TOKENS, 256>>>(h, ln1_w + i * EMB, ln1_b + i * EMB, xnH, xnL);

        wgemm<128,128,64,64,32,EPI_QKV,false><<<dim3(3*EMB/128, TOKENS/128), 256, SM_BIG>>>(
            xnH, xnL, EMB,
            qkvTH + (size_t)i * 3 * EMB * EMB, qkvTL + (size_t)i * 3 * EMB * EMB, EMB,
            nullptr, 3 * EMB, EMB, 0, 0, 0,
            qkv_b + (size_t)i * 3 * EMB, nullptr, nullptr,
            qH, qL, kH, kL, vH, vL, 0.f);

        rel_kernel<<<BHEADS * SEQ, 64>>>(qH, qL,
                                         rph + (size_t)i * 63 * HD, rpw + (size_t)i * 63 * HD,
                                         relh, relw);

        // S = scale * q @ k^T + rel_h + rel_w  (batched over 48 bh; K=64 -> single k-block)
        wgemm<128,128,64,64,32,EPI_SREL,false><<<dim3(SEQ/128, SEQ/128, BHEADS), 256, SM_BIG>>>(
            qH, qL, HD, kH, kL, HD, S, SEQ, HD,
            (size_t)SEQ * HD, (size_t)SEQ * HD, (size_t)SEQ * SEQ,
            nullptr, relh, relw,
            nullptr, nullptr, nullptr, nullptr, nullptr, nullptr, scale);

        softmax_kernel<<<BHEADS * SEQ, 256>>>(S);

        // O = P @ v ; P planes live inside g_S rows (hi at +0, lo at +1024, row stride 2048)
        wgemm<128,64,64,32,32,EPI_AV,true><<<dim3(1, SEQ/128, BHEADS), 256, SM_AV>>>(
            (const bf16*)S, (const bf16*)S + SEQ, 2 * SEQ,
            vH, vL, HD,
            nullptr, HD, SEQ,
            (size_t)SEQ * 2 * SEQ, (size_t)SEQ * HD, 0,
            nullptr, nullptr, nullptr,
            attnH, attnL, nullptr, nullptr, nullptr, nullptr, 0.f);

        wgemm<128,128,64,64,32,EPI_BIASRES,false><<<dim3(EMB/128, TOKENS/128), 256, SM_BIG>>>(
            attnH, attnL, EMB,
            projTH + (size_t)i * EMB * EMB, projTL + (size_t)i * EMB * EMB, EMB,
            h, EMB, EMB, 0, 0, 0,
            proj_b + (size_t)i * EMB, h, nullptr,
            nullptr, nullptr, nullptr, nullptr, nullptr, nullptr, 0.f);

        ln_kernel<<<TOKENS, 256>>>(h, ln2_w + i * EMB, ln2_b + i * EMB, xnH, xnL);

        wgemm<128,128,64,64,32,EPI_GELU,false><<<dim3(MLPD/128, TOKENS/128), 256, SM_BIG>>>(
            xnH, xnL, EMB,
            fc1TH + (size_t)i * MLPD * EMB, fc1TL + (size_t)i * MLPD * EMB, EMB,
            nullptr, MLPD, EMB, 0, 0, 0,
            fc1_b + (size_t)i * MLPD, nullptr, nullptr,
            mlpH, mlpL, nullptr, nullptr, nullptr, nullptr, 0.f);

        float* dst = (i == 3) ? (float*)d_out : h;
        wgemm<128,128,64,64,32,EPI_BIASRES,false><<<dim3(EMB/128, TOKENS/128), 256, SM_BIG>>>(
            mlpH, mlpL, MLPD,
            fc2TH + (size_t)i * EMB * MLPD, fc2TL + (size_t)i * EMB * MLPD, MLPD,
            dst, EMB, MLPD, 0, 0, 0,
            fc2_b + (size_t)i * EMB, h, nullptr,
            nullptr, nullptr, nullptr, nullptr, nullptr, nullptr, 0.f);
    }
}